// round 8
// baseline (speedup 1.0000x reference)
#include <cuda_runtime.h>
#include <cstdint>

// EdgeBlock fused MLP, TF32 mma.sync. Round 8:
//  - SX_STRIDE 132: conflict-free AND 16B-aligned rows -> STS.128 staging
//  - pair-packed B weights (float4 = 2 fragments) -> LDG.128, half the loads
//  - h epilogue STS.64, float2 bias loads, no index smem stage
// x = [edges(32) | nodes[send](32) | nodes[recv](32) | globals[batch](16)]  (K=112)
// h = relu(x @ W1 + b1) (64);  y = h @ W2 + b2 (32)

#define TILE_M 128
#define NTHREADS 256

#define SX_STRIDE 132       // g*132+c mod 32 = g*4+c -> conflict-free; 528B rows, 16B aligned
#define SH_STRIDE 68        // 68 mod 32 = 4 -> conflict-free; 272B rows
#define SMEM_FLOATS (TILE_M * SX_STRIDE)    // 16896
#define SMEM_BYTES  (SMEM_FLOATS * 4)       // 67584 -> 3 CTAs/SM

// pair-packed weights: [ks][ntp][lane] -> float4 {b0_even, b1_even, b0_odd, b1_odd}
__device__ float4 d_W1P[14 * 4 * 32];
__device__ float4 d_W2P[8 * 2 * 32];

__device__ __forceinline__ float tf32_rna(float x) {
    unsigned u;
    asm("cvt.rna.tf32.f32 %0, %1;" : "=r"(u) : "f"(x));
    return __uint_as_float(u);
}

__device__ __forceinline__ void mma_tf32_16x8x8(float* c, const unsigned* a,
                                                unsigned b0, unsigned b1) {
    asm volatile(
        "mma.sync.aligned.m16n8k8.row.col.f32.tf32.tf32.f32 "
        "{%0,%1,%2,%3}, {%4,%5,%6,%7}, {%8,%9}, {%0,%1,%2,%3};"
        : "+f"(c[0]), "+f"(c[1]), "+f"(c[2]), "+f"(c[3])
        : "r"(a[0]), "r"(a[1]), "r"(a[2]), "r"(a[3]), "r"(b0), "r"(b1));
}

__global__ void prep_weights(const float* __restrict__ W1,
                             const float* __restrict__ W2) {
    int i = blockIdx.x * blockDim.x + threadIdx.x;
    if (i < 14 * 4 * 32) {
        int lane = i & 31, ntp = (i >> 5) & 3, ks = i >> 7;
        int g = lane >> 2, c = lane & 3;
        int ne = 2 * ntp, no = 2 * ntp + 1;
        float4 v;
        v.x = tf32_rna(W1[(ks * 8 + c) * 64 + ne * 8 + g]);
        v.y = tf32_rna(W1[(ks * 8 + c + 4) * 64 + ne * 8 + g]);
        v.z = tf32_rna(W1[(ks * 8 + c) * 64 + no * 8 + g]);
        v.w = tf32_rna(W1[(ks * 8 + c + 4) * 64 + no * 8 + g]);
        d_W1P[i] = v;
    }
    if (i < 8 * 2 * 32) {
        int lane = i & 31, ntp = (i >> 5) & 1, ks = i >> 6;
        int g = lane >> 2, c = lane & 3;
        int ne = 2 * ntp, no = 2 * ntp + 1;
        float4 v;
        v.x = tf32_rna(W2[(ks * 8 + c) * 32 + ne * 8 + g]);
        v.y = tf32_rna(W2[(ks * 8 + c + 4) * 32 + ne * 8 + g]);
        v.z = tf32_rna(W2[(ks * 8 + c) * 32 + no * 8 + g]);
        v.w = tf32_rna(W2[(ks * 8 + c + 4) * 32 + no * 8 + g]);
        d_W2P[i] = v;
    }
}

__global__ void __launch_bounds__(NTHREADS, 3)
edgeblock_kernel(const float* __restrict__ nodes,
                 const float* __restrict__ edges,
                 const float* __restrict__ graph_globals,
                 const int*   __restrict__ send,
                 const int*   __restrict__ recv,
                 const int*   __restrict__ batch_edges,
                 const float* __restrict__ b1,
                 const float* __restrict__ b2,
                 float*       __restrict__ out) {
    extern __shared__ float sm[];
    float* sX = sm;                      // [128][132] tf32 (aliased by sH)

    const int t  = threadIdx.x;
    const int e0 = blockIdx.x * TILE_M;

    // ---- stage x tile (float4 LDG -> tf32 -> STS.128) ----
    for (int i = t; i < TILE_M * 8; i += NTHREADS) {
        int e = i >> 3, seg = i & 7;
        float4 v = *reinterpret_cast<const float4*>(edges + (size_t)(e0 + e) * 32 + seg * 4);
        float4 o = make_float4(tf32_rna(v.x), tf32_rna(v.y), tf32_rna(v.z), tf32_rna(v.w));
        *reinterpret_cast<float4*>(sX + e * SX_STRIDE + seg * 4) = o;
    }
    for (int i = t; i < TILE_M * 8; i += NTHREADS) {
        int e = i >> 3, seg = i & 7;
        int n = __ldg(send + e0 + e);
        float4 v = *reinterpret_cast<const float4*>(nodes + (size_t)n * 32 + seg * 4);
        float4 o = make_float4(tf32_rna(v.x), tf32_rna(v.y), tf32_rna(v.z), tf32_rna(v.w));
        *reinterpret_cast<float4*>(sX + e * SX_STRIDE + 32 + seg * 4) = o;
    }
    for (int i = t; i < TILE_M * 8; i += NTHREADS) {
        int e = i >> 3, seg = i & 7;
        int n = __ldg(recv + e0 + e);
        float4 v = *reinterpret_cast<const float4*>(nodes + (size_t)n * 32 + seg * 4);
        float4 o = make_float4(tf32_rna(v.x), tf32_rna(v.y), tf32_rna(v.z), tf32_rna(v.w));
        *reinterpret_cast<float4*>(sX + e * SX_STRIDE + 64 + seg * 4) = o;
    }
    for (int i = t; i < TILE_M * 4; i += NTHREADS) {
        int e = i >> 2, seg = i & 3;
        int g = __ldg(batch_edges + e0 + e);
        float4 v = *reinterpret_cast<const float4*>(graph_globals + (size_t)g * 16 + seg * 4);
        float4 o = make_float4(tf32_rna(v.x), tf32_rna(v.y), tf32_rna(v.z), tf32_rna(v.w));
        *reinterpret_cast<float4*>(sX + e * SX_STRIDE + 96 + seg * 4) = o;
    }
    __syncthreads();

    // ---- layer 1: [128,112] @ [112,64]; warp w owns rows [w*16, w*16+16) ----
    const int lane = t & 31;
    const int w    = t >> 5;
    const int g    = lane >> 2;
    const int c    = lane & 3;
    const int r    = w * 16 + g;

    const float4* w1p = d_W1P + lane;   // + (ks*4+ntp)*32
    const float4* w2p = d_W2P + lane;   // + (ks*2+ntp)*32

    float acc[8][4];
#pragma unroll
    for (int nt = 0; nt < 8; nt++)
#pragma unroll
        for (int q = 0; q < 4; q++) acc[nt][q] = 0.0f;

#pragma unroll
    for (int ks = 0; ks < 14; ks++) {
        const int k = ks * 8;
        unsigned a[4];
        a[0] = __float_as_uint(sX[r * SX_STRIDE + k + c]);
        a[1] = __float_as_uint(sX[(r + 8) * SX_STRIDE + k + c]);
        a[2] = __float_as_uint(sX[r * SX_STRIDE + k + c + 4]);
        a[3] = __float_as_uint(sX[(r + 8) * SX_STRIDE + k + c + 4]);
#pragma unroll
        for (int ntp = 0; ntp < 4; ntp++) {
            float4 b = __ldg(w1p + (ks * 4 + ntp) * 32);
            mma_tf32_16x8x8(acc[2 * ntp],     a, __float_as_uint(b.x), __float_as_uint(b.y));
            mma_tf32_16x8x8(acc[2 * ntp + 1], a, __float_as_uint(b.z), __float_as_uint(b.w));
        }
    }
    __syncthreads();   // done reading sX; sH aliases it

    // ---- bias + relu + tf32 -> smem h (STS.64) ----
    float* sH = sm;   // [128][68]
#pragma unroll
    for (int nt = 0; nt < 8; nt++) {
        int col = nt * 8 + 2 * c;
        float2 bb = __ldg(reinterpret_cast<const float2*>(b1 + col));
        float2 h0 = make_float2(tf32_rna(fmaxf(acc[nt][0] + bb.x, 0.0f)),
                                tf32_rna(fmaxf(acc[nt][1] + bb.y, 0.0f)));
        float2 h1 = make_float2(tf32_rna(fmaxf(acc[nt][2] + bb.x, 0.0f)),
                                tf32_rna(fmaxf(acc[nt][3] + bb.y, 0.0f)));
        *reinterpret_cast<float2*>(sH + r * SH_STRIDE + col)       = h0;
        *reinterpret_cast<float2*>(sH + (r + 8) * SH_STRIDE + col) = h1;
    }
    __syncthreads();

    // ---- layer 2: [128,64] @ [64,32] ----
    float d2[4][4];
#pragma unroll
    for (int nt = 0; nt < 4; nt++)
#pragma unroll
        for (int q = 0; q < 4; q++) d2[nt][q] = 0.0f;

#pragma unroll
    for (int ks = 0; ks < 8; ks++) {
        const int k = ks * 8;
        unsigned a[4];
        a[0] = __float_as_uint(sH[r * SH_STRIDE + k + c]);
        a[1] = __float_as_uint(sH[(r + 8) * SH_STRIDE + k + c]);
        a[2] = __float_as_uint(sH[r * SH_STRIDE + k + c + 4]);
        a[3] = __float_as_uint(sH[(r + 8) * SH_STRIDE + k + c + 4]);
#pragma unroll
        for (int ntp = 0; ntp < 2; ntp++) {
            float4 b = __ldg(w2p + (ks * 2 + ntp) * 32);
            mma_tf32_16x8x8(d2[2 * ntp],     a, __float_as_uint(b.x), __float_as_uint(b.y));
            mma_tf32_16x8x8(d2[2 * ntp + 1], a, __float_as_uint(b.z), __float_as_uint(b.w));
        }
    }

    // ---- epilogue: bias + store out[E,32] ----
#pragma unroll
    for (int nt = 0; nt < 4; nt++) {
        int col = nt * 8 + 2 * c;
        float2 bb = __ldg(reinterpret_cast<const float2*>(b2 + col));
        float2 v0 = make_float2(d2[nt][0] + bb.x, d2[nt][1] + bb.y);
        float2 v1 = make_float2(d2[nt][2] + bb.x, d2[nt][3] + bb.y);
        *reinterpret_cast<float2*>(out + (size_t)(e0 + r) * 32 + col)     = v0;
        *reinterpret_cast<float2*>(out + (size_t)(e0 + r + 8) * 32 + col) = v1;
    }
}

extern "C" void kernel_launch(void* const* d_in, const int* in_sizes, int n_in,
                              void* d_out, int out_size) {
    const float* nodes         = (const float*)d_in[0];
    const float* edges         = (const float*)d_in[1];
    const float* graph_globals = (const float*)d_in[2];
    const int*   send          = (const int*)d_in[3];
    const int*   recv          = (const int*)d_in[4];
    const int*   batch_edges   = (const int*)d_in[5];
    const float* W1            = (const float*)d_in[6];
    const float* b1            = (const float*)d_in[7];
    const float* W2            = (const float*)d_in[8];
    const float* b2            = (const float*)d_in[9];
    float*       out           = (float*)d_out;

    const int n_edges = in_sizes[1] / 32;          // 1,600,000
    const int grid    = (n_edges + TILE_M - 1) / TILE_M;

    prep_weights<<<(14 * 4 * 32 + 255) / 256, 256>>>(W1, W2);

    cudaFuncSetAttribute(edgeblock_kernel,
                         cudaFuncAttributeMaxDynamicSharedMemorySize, SMEM_BYTES);
    edgeblock_kernel<<<grid, NTHREADS, SMEM_BYTES>>>(
        nodes, edges, graph_globals, send, recv, batch_edges,
        b1, b2, out);
}